// round 1
// baseline (speedup 1.0000x reference)
#include <cuda_runtime.h>
#include <math.h>

// Problem constants
#define B_SZ   32
#define T_STEPS 128
#define I_CH   16
#define N_DIM  512

// Tiling
#define TK  64            // k (output-neuron) tile per block
#define BH  16            // batches per block
#define KB  32            // reduction-chunk depth staged in smem
#define NT  256           // 4 gates * TK
#define THREADS 256

// c-state scratch (allowed: __device__ global, no allocation)
__device__ float g_c[B_SZ * I_CH * N_DIM];

struct Params {
    const float* x;
    const float* U[4];
    const float* W[4];
    const float* bias[4];
    float* out;
};

__global__ void zero_c_kernel() {
    int idx = blockIdx.x * blockDim.x + threadIdx.x;
    if (idx < B_SZ * I_CH * N_DIM) g_c[idx] = 0.0f;
}

__global__ __launch_bounds__(THREADS)
void step_kernel(Params p, int t) {
    const int kblk  = blockIdx.x;          // 0..7
    const int i_ch  = blockIdx.y;          // 0..15
    const int bgrp  = blockIdx.z;          // 0..1
    const int k0    = kblk * TK;
    const int bbase = bgrp * BH;
    const int tid   = threadIdx.x;

    extern __shared__ float smem[];
    float* h_s = smem;                      // BH * N_DIM  = 8192 floats (32 KB)
    float* w_s = smem + BH * N_DIM;         // KB * NT     = 8192 floats (32 KB); reused as s_pre

    __shared__ float u_s[4 * TK];
    __shared__ float bias_s[4 * TK];
    __shared__ float x_s[BH];

    // --- small per-block constants: U slice, bias slice, x_t ---
    {
        int g  = tid >> 6;          // gate
        int kk = tid & 63;
        u_s[tid]    = p.U[g][i_ch * N_DIM + k0 + kk];
        bias_s[tid] = p.bias[g][i_ch * N_DIM + k0 + kk];
        if (tid < BH) {
            int bg = bbase + tid;
            x_s[tid] = p.x[(bg * T_STEPS + t) * I_CH + i_ch];
        }
    }

    // --- load h (previous step's output, or zeros at t==0) into smem ---
    if (t == 0) {
        #pragma unroll
        for (int it = 0; it < 8; ++it) {
            int lin = it * THREADS + tid;   // 2048 float4 total
            reinterpret_cast<float4*>(h_s)[lin] = make_float4(0.f, 0.f, 0.f, 0.f);
        }
    } else {
        #pragma unroll
        for (int it = 0; it < 8; ++it) {
            int lin = it * THREADS + tid;
            int bl  = lin >> 7;             // local batch 0..15
            int v   = lin & 127;            // float4 index within N
            const float4* src = reinterpret_cast<const float4*>(
                p.out + (((size_t)(bbase + bl) * T_STEPS + (t - 1)) * I_CH + i_ch) * N_DIM) + v;
            reinterpret_cast<float4*>(h_s)[lin] = *src;
        }
    }

    // --- GEMM: acc[b4][c4], M=16, C=256 (4 gates x 64), K=512 ---
    float acc[4][4];
    #pragma unroll
    for (int a = 0; a < 4; ++a)
        #pragma unroll
        for (int b = 0; b < 4; ++b) acc[a][b] = 0.0f;

    const int tc = tid & 63;    // c-tile position (c = tc*4 .. tc*4+3)
    const int tb = tid >> 6;    // b-tile position (b = tb*4 .. tb*4+3)

    for (int r0 = 0; r0 < N_DIM; r0 += KB) {
        __syncthreads();  // protect w_s from prior-iter readers; first iter covers h_s
        // stage W chunk: 4 gates x KB rows x TK cols = 2048 float4
        #pragma unroll
        for (int it = 0; it < 8; ++it) {
            int lin = it * THREADS + tid;
            int g   = lin >> 9;
            int rem = lin & 511;
            int r   = rem >> 4;
            int f4  = rem & 15;
            const float4* src = reinterpret_cast<const float4*>(
                p.W[g] + ((size_t)i_ch * N_DIM + (r0 + r)) * N_DIM + k0) + f4;
            reinterpret_cast<float4*>(w_s)[r * (NT / 4) + g * (TK / 4) + f4] = *src;
        }
        __syncthreads();

        #pragma unroll 8
        for (int r = 0; r < KB; ++r) {
            float4 wv = reinterpret_cast<const float4*>(w_s + r * NT)[tc];
            float h0 = h_s[(tb * 4 + 0) * N_DIM + r0 + r];
            float h1 = h_s[(tb * 4 + 1) * N_DIM + r0 + r];
            float h2 = h_s[(tb * 4 + 2) * N_DIM + r0 + r];
            float h3 = h_s[(tb * 4 + 3) * N_DIM + r0 + r];
            acc[0][0] += h0 * wv.x; acc[0][1] += h0 * wv.y; acc[0][2] += h0 * wv.z; acc[0][3] += h0 * wv.w;
            acc[1][0] += h1 * wv.x; acc[1][1] += h1 * wv.y; acc[1][2] += h1 * wv.z; acc[1][3] += h1 * wv.w;
            acc[2][0] += h2 * wv.x; acc[2][1] += h2 * wv.y; acc[2][2] += h2 * wv.z; acc[2][3] += h2 * wv.w;
            acc[3][0] += h3 * wv.x; acc[3][1] += h3 * wv.y; acc[3][2] += h3 * wv.z; acc[3][3] += h3 * wv.w;
        }
    }

    // --- stage pre-activations so each thread can see all 4 gates at one (b,k) ---
    __syncthreads();
    float* s_pre = w_s;   // BH * NT = 4096 floats, fits in w_s
    #pragma unroll
    for (int bb = 0; bb < 4; ++bb) {
        float4 v = make_float4(acc[bb][0], acc[bb][1], acc[bb][2], acc[bb][3]);
        reinterpret_cast<float4*>(s_pre + (tb * 4 + bb) * NT)[tc] = v;
    }
    __syncthreads();

    // --- pointwise neuron update: 16 b x 64 k = 1024 elems, 4 per thread ---
    const float DT = 0.01f;
    const float A_OUT = 0.9900498337491681f;      // exp(-0.01)
    const float ONE_MINUS_A_OUT = 0.009950166250831947f;
    #pragma unroll
    for (int e = 0; e < 4; ++e) {
        int lin = e * THREADS + tid;
        int bl  = lin >> 6;          // local batch
        int kk  = lin & 63;          // k within tile

        float xb = x_s[bl];
        float pj = s_pre[bl * NT +          kk] + xb * u_s[         kk] + bias_s[         kk];
        float pi = s_pre[bl * NT +   TK +   kk] + xb * u_s[  TK +   kk] + bias_s[  TK +   kk];
        float pf = s_pre[bl * NT + 2*TK +   kk] + xb * u_s[2*TK +   kk] + bias_s[2*TK +   kk];
        float po = s_pre[bl * NT + 3*TK +   kk] + xb * u_s[3*TK +   kk] + bias_s[3*TK +   kk];

        float j  = tanhf(pj);
        float ig = 1.0f / (1.0f + expf(-pi));
        float fg = 1.0f / (1.0f + expf(-pf));
        float og = 1.0f / (1.0f + expf(-po));

        float h_old = h_s[bl * N_DIM + k0 + kk];

        float alpha_m = expf(-7.8125e-5f * j);        // exp(-(dt/tau_m)*0.5*j)
        float ro      = expf(-1.5625e-4f * ig);       // exp(-(dt/tau_adp)*0.5*i)
        float b_ad    = ro * 0.1f + (1.0f - ro) * ig;
        float Bth     = 0.04f + 1.8f * b_ad;
        float mem     = j * alpha_m + (1.0f - alpha_m) * h_old - Bth * ig * DT;
        float spike   = (mem - Bth) > 0.0f ? 1.0f : 0.0f;
        float mem_out = mem * A_OUT + ONE_MINUS_A_OUT * spike + 0.08f;

        int bg = bbase + bl;
        size_t cidx = ((size_t)bg * I_CH + i_ch) * N_DIM + k0 + kk;
        float c_new = g_c[cidx] * fg + ig * spike * mem_out;
        g_c[cidx] = c_new;
        float h_new = og * tanhf(c_new);

        p.out[(((size_t)bg * T_STEPS + t) * I_CH + i_ch) * N_DIM + k0 + kk] = h_new;
    }
}

__global__ void finalize_kernel(float* out) {
    int idx = blockIdx.x * blockDim.x + threadIdx.x;
    const int BIN = B_SZ * I_CH * N_DIM;
    if (idx >= BIN) return;
    int b   = idx / (I_CH * N_DIM);
    int rem = idx % (I_CH * N_DIM);
    float* h_fin = out + (size_t)B_SZ * T_STEPS * I_CH * N_DIM;
    float* c_fin = h_fin + BIN;
    h_fin[idx] = out[((size_t)b * T_STEPS + (T_STEPS - 1)) * I_CH * N_DIM + rem];
    c_fin[idx] = g_c[idx];
}

extern "C" void kernel_launch(void* const* d_in, const int* in_sizes, int n_in,
                              void* d_out, int out_size) {
    Params p;
    p.x = (const float*)d_in[0];
    for (int g = 0; g < 4; ++g) {
        p.U[g]    = (const float*)d_in[1 + g];   // U_j, U_i, U_f, U_o
        p.W[g]    = (const float*)d_in[5 + g];   // W_j, W_i, W_f, W_o
        p.bias[g] = (const float*)d_in[9 + g];   // b_j, b_i, b_f, b_o
    }
    p.out = (float*)d_out;

    const int smem = (BH * N_DIM + KB * NT) * (int)sizeof(float);   // 64 KB
    cudaFuncSetAttribute(step_kernel, cudaFuncAttributeMaxDynamicSharedMemorySize, smem);

    zero_c_kernel<<<(B_SZ * I_CH * N_DIM + 255) / 256, 256>>>();

    dim3 grid(N_DIM / TK, I_CH, B_SZ / BH);   // 8 x 16 x 2 = 256 blocks
    for (int t = 0; t < T_STEPS; ++t) {
        step_kernel<<<grid, THREADS, smem>>>(p, t);
    }

    finalize_kernel<<<(B_SZ * I_CH * N_DIM + 255) / 256, 256>>>(p.out);
}